// round 1
// baseline (speedup 1.0000x reference)
#include <cuda_runtime.h>
#include <cuda_bf16.h>
#include <math.h>

// Problem constants (fixed by setup_inputs)
#define C_CAPS 256
#define K_CAPS 64
#define H_DIM  1024
#define MAX_ITERS 4

// Scratch (device globals — no allocation allowed)
__device__ __align__(16) float g_b[C_CAPS * K_CAPS];      // routing logits  [C,K]
__device__ __align__(16) float g_e[C_CAPS * H_DIM];       // weighted enc sum [C,H]
__device__ __align__(16) float g_chat[C_CAPS * H_DIM];    // pre-squash      [C,H]
__device__ __align__(16) float g_g[C_CAPS * H_DIM];       // W^T c           [C,H]

// ---------------------------------------------------------------------------
// zero b
__global__ void zero_b_kernel() {
    int i = blockIdx.x * blockDim.x + threadIdx.x;
    if (i < C_CAPS * K_CAPS) g_b[i] = 0.0f;
}

// ---------------------------------------------------------------------------
// Per capsule c: d = softmax(b[c,:]); e[c,h] = sum_k d[k] * enc[c,k,h]
__global__ void reduce_e_kernel(const float* __restrict__ enc,
                                const int* __restrict__ itern, int it) {
    if (it >= *itern) return;
    int c = blockIdx.x;
    int t = threadIdx.x;
    __shared__ float dsh[K_CAPS];
    if (t < K_CAPS) dsh[t] = g_b[c * K_CAPS + t];
    __syncthreads();
    if (t == 0) {
        float m = dsh[0];
        #pragma unroll
        for (int k = 1; k < K_CAPS; k++) m = fmaxf(m, dsh[k]);
        float s = 0.0f;
        #pragma unroll
        for (int k = 0; k < K_CAPS; k++) { float e = expf(dsh[k] - m); dsh[k] = e; s += e; }
        float inv = 1.0f / s;
        #pragma unroll
        for (int k = 0; k < K_CAPS; k++) dsh[k] *= inv;
    }
    __syncthreads();
    const float* base = enc + (size_t)c * K_CAPS * H_DIM;
    for (int h = t; h < H_DIM; h += blockDim.x) {
        float s = 0.0f;
        #pragma unroll 8
        for (int k = 0; k < K_CAPS; k++)
            s += dsh[k] * base[k * H_DIM + h];
        g_e[c * H_DIM + h] = s;
    }
}

// ---------------------------------------------------------------------------
// GEMM NT: chat[m,n] = sum_k e[m,k] * W[n,k]    (M=256, N=1024, K=1024)
// Block tile 32x64, BK=32, 128 threads, 4x4 micro-tile.
__global__ void gemm_nt_kernel(const float* __restrict__ W,
                               const int* __restrict__ itern, int it) {
    if (it >= *itern) return;
    __shared__ float As[32][33];   // As[kk][m]
    __shared__ float Bs[64][33];   // Bs[n][kk]
    int m0 = blockIdx.x * 32;
    int n0 = blockIdx.y * 64;
    int t = threadIdx.x;
    int tx = t & 15;   // n group
    int ty = t >> 4;   // m group (0..7)
    float acc[4][4] = {};

    for (int k0 = 0; k0 < H_DIM; k0 += 32) {
        // load A tile (32x32): each thread 2 float4
        {
            int r = t >> 2;            // 0..31
            int c4 = (t & 3) * 4;      // 0,4,8,12
            #pragma unroll
            for (int rep = 0; rep < 2; rep++) {
                int cc = c4 + rep * 16;
                float4 v = *reinterpret_cast<const float4*>(&g_e[(m0 + r) * H_DIM + k0 + cc]);
                As[cc + 0][r] = v.x; As[cc + 1][r] = v.y;
                As[cc + 2][r] = v.z; As[cc + 3][r] = v.w;
            }
        }
        // load B tile (64 n-rows x 32 kk): each thread 4 float4
        {
            int n  = t >> 1;           // 0..63
            int b0 = (t & 1) * 16;     // 0 or 16
            #pragma unroll
            for (int rep = 0; rep < 4; rep++) {
                int cc = b0 + rep * 4;
                float4 v = *reinterpret_cast<const float4*>(&W[(size_t)(n0 + n) * H_DIM + k0 + cc]);
                Bs[n][cc + 0] = v.x; Bs[n][cc + 1] = v.y;
                Bs[n][cc + 2] = v.z; Bs[n][cc + 3] = v.w;
            }
        }
        __syncthreads();
        #pragma unroll
        for (int kk = 0; kk < 32; kk++) {
            float a[4], b[4];
            #pragma unroll
            for (int i = 0; i < 4; i++) a[i] = As[kk][ty * 4 + i];
            #pragma unroll
            for (int j = 0; j < 4; j++) b[j] = Bs[tx * 4 + j][kk];
            #pragma unroll
            for (int i = 0; i < 4; i++)
                #pragma unroll
                for (int j = 0; j < 4; j++)
                    acc[i][j] += a[i] * b[j];
        }
        __syncthreads();
    }
    #pragma unroll
    for (int i = 0; i < 4; i++)
        #pragma unroll
        for (int j = 0; j < 4; j++)
            g_chat[(m0 + ty * 4 + i) * H_DIM + n0 + tx * 4 + j] = acc[i][j];
}

// ---------------------------------------------------------------------------
// squash: out[c,:] = (norm/(1+norm)) * chat[c,:] / sqrt(norm), norm = sum chat^2
__global__ void squash_kernel(float* __restrict__ out,
                              const int* __restrict__ itern, int it) {
    if (it >= *itern) return;
    int c = blockIdx.x;
    int t = threadIdx.x;
    __shared__ float red[8];
    float s = 0.0f;
    for (int h = t; h < H_DIM; h += blockDim.x) {
        float v = g_chat[c * H_DIM + h];
        s += v * v;
    }
    #pragma unroll
    for (int o = 16; o; o >>= 1) s += __shfl_down_sync(0xffffffffu, s, o);
    if ((t & 31) == 0) red[t >> 5] = s;
    __syncthreads();
    if (t < 32) {
        float v = (t < 8) ? red[t] : 0.0f;
        #pragma unroll
        for (int o = 4; o; o >>= 1) v += __shfl_down_sync(0xffffffffu, v, o);
        if (t == 0) red[0] = v;
    }
    __syncthreads();
    float norm = red[0];
    float scale = (norm / (1.0f + norm)) * rsqrtf(norm);
    for (int h = t; h < H_DIM; h += blockDim.x)
        out[c * H_DIM + h] = scale * g_chat[c * H_DIM + h];
}

// ---------------------------------------------------------------------------
// GEMM NN: g[m,n] = sum_k cout[m,k] * W[k,n]    (M=256, N=1024, K=1024)
__global__ void gemm_nn_kernel(const float* __restrict__ W,
                               const float* __restrict__ Cin,
                               const int* __restrict__ itern, int it) {
    if (it >= *itern) return;
    __shared__ float As[32][33];   // As[kk][m]
    __shared__ float Bs[32][64];   // Bs[kk][n] — natural, float4-friendly
    int m0 = blockIdx.x * 32;
    int n0 = blockIdx.y * 64;
    int t = threadIdx.x;
    int tx = t & 15;
    int ty = t >> 4;
    float acc[4][4] = {};

    for (int k0 = 0; k0 < H_DIM; k0 += 32) {
        // A tile: Cin[m0+r][k0+...]
        {
            int r = t >> 2;
            int c4 = (t & 3) * 4;
            #pragma unroll
            for (int rep = 0; rep < 2; rep++) {
                int cc = c4 + rep * 16;
                float4 v = *reinterpret_cast<const float4*>(&Cin[(m0 + r) * H_DIM + k0 + cc]);
                As[cc + 0][r] = v.x; As[cc + 1][r] = v.y;
                As[cc + 2][r] = v.z; As[cc + 3][r] = v.w;
            }
        }
        // B tile: W[k0+kk][n0+n] contiguous in n
        {
            int kk = t >> 2;            // 0..31
            int nb = (t & 3) * 4;       // 0,4,8,12
            #pragma unroll
            for (int rep = 0; rep < 4; rep++) {
                int nn = nb + rep * 16;
                float4 v = *reinterpret_cast<const float4*>(&W[(size_t)(k0 + kk) * H_DIM + n0 + nn]);
                *reinterpret_cast<float4*>(&Bs[kk][nn]) = v;
            }
        }
        __syncthreads();
        #pragma unroll
        for (int kk = 0; kk < 32; kk++) {
            float a[4];
            #pragma unroll
            for (int i = 0; i < 4; i++) a[i] = As[kk][ty * 4 + i];
            float4 bv = *reinterpret_cast<const float4*>(&Bs[kk][tx * 4]);
            float b[4] = {bv.x, bv.y, bv.z, bv.w};
            #pragma unroll
            for (int i = 0; i < 4; i++)
                #pragma unroll
                for (int j = 0; j < 4; j++)
                    acc[i][j] += a[i] * b[j];
        }
        __syncthreads();
    }
    #pragma unroll
    for (int i = 0; i < 4; i++)
        #pragma unroll
        for (int j = 0; j < 4; j++)
            g_g[(m0 + ty * 4 + i) * H_DIM + n0 + tx * 4 + j] = acc[i][j];
}

// ---------------------------------------------------------------------------
// b[c,k] += dot(enc[c,k,:], g[c,:])   — skipped on the last iteration (dead)
__global__ void update_b_kernel(const float* __restrict__ enc,
                                const int* __restrict__ itern, int it) {
    if (it + 1 >= *itern) return;
    int c = blockIdx.x;
    int t = threadIdx.x;
    int warp = t >> 5, lane = t & 31;
    __shared__ __align__(16) float gsh[H_DIM];
    for (int h = t; h < H_DIM; h += blockDim.x) gsh[h] = g_g[c * H_DIM + h];
    __syncthreads();
    const float4* g4 = reinterpret_cast<const float4*>(gsh);
    for (int k = warp; k < K_CAPS; k += 8) {
        const float4* row4 = reinterpret_cast<const float4*>(
            enc + ((size_t)c * K_CAPS + k) * H_DIM);
        float s = 0.0f;
        #pragma unroll
        for (int i = lane; i < H_DIM / 4; i += 32) {
            float4 a = row4[i];
            float4 b = g4[i];
            s += a.x * b.x + a.y * b.y + a.z * b.z + a.w * b.w;
        }
        #pragma unroll
        for (int o = 16; o; o >>= 1) s += __shfl_down_sync(0xffffffffu, s, o);
        if (lane == 0) g_b[c * K_CAPS + k] += s;
    }
}

// ---------------------------------------------------------------------------
extern "C" void kernel_launch(void* const* d_in, const int* in_sizes, int n_in,
                              void* d_out, int out_size) {
    const float* enc   = (const float*)d_in[0];   // [C, K, H]
    const float* W     = (const float*)d_in[1];   // [H, H]
    const int*   itern = (const int*)d_in[2];     // scalar iter_routing
    float* out = (float*)d_out;                   // [C, H]

    zero_b_kernel<<<(C_CAPS * K_CAPS + 255) / 256, 256>>>();

    dim3 gemm_grid(C_CAPS / 32, H_DIM / 64);      // (8, 16) = 128 blocks
    for (int it = 0; it < MAX_ITERS; it++) {
        reduce_e_kernel<<<C_CAPS, 256>>>(enc, itern, it);
        gemm_nt_kernel<<<gemm_grid, 128>>>(W, itern, it);
        squash_kernel<<<C_CAPS, 256>>>(out, itern, it);
        gemm_nn_kernel<<<gemm_grid, 128>>>(W, out, itern, it);
        update_b_kernel<<<C_CAPS, 256>>>(enc, itern, it);
    }
}

// round 2
// speedup vs baseline: 1.4191x; 1.4191x over previous
#include <cuda_runtime.h>
#include <cuda_bf16.h>
#include <math.h>

#define C_CAPS 256
#define K_CAPS 64
#define H_DIM  1024
#define MAX_ITERS 4

// Scratch (device globals — no allocation allowed)
__device__ __align__(16) float g_b[C_CAPS * K_CAPS];      // routing logits  [C,K]
__device__ __align__(16) float g_e[C_CAPS * H_DIM];       // weighted enc sum [C,H]
__device__ __align__(16) float g_chat[C_CAPS * H_DIM];    // pre-squash      [C,H]
__device__ __align__(16) float g_g[C_CAPS * H_DIM];       // W^T c           [C,H]

// ---------------------------------------------------------------------------
// Fused routing step for capsule c:
//   (it>0)  b[c,k] += dot(enc[c,k,:], g[c,:]);  d = softmax(b[c,:])
//   (it==0) b = 0; d = 1/K
//   e[c,:] = sum_k d[k] * enc[c,k,:]
__global__ void __launch_bounds__(256) route_kernel(
        const float* __restrict__ enc,
        const int* __restrict__ itern, int it) {
    if (it >= *itern) return;
    int c = blockIdx.x;
    int t = threadIdx.x;
    int warp = t >> 5, lane = t & 31;
    __shared__ __align__(16) float gsh[H_DIM];
    __shared__ float dsh[K_CAPS];
    const float* base = enc + (size_t)c * K_CAPS * H_DIM;

    if (it == 0) {
        if (t < K_CAPS) { dsh[t] = 1.0f / (float)K_CAPS; g_b[c * K_CAPS + t] = 0.0f; }
        __syncthreads();
    } else {
        // stage g = W^T c into smem
        for (int h = t; h < H_DIM; h += 256) gsh[h] = g_g[c * H_DIM + h];
        __syncthreads();
        const float4* g4 = reinterpret_cast<const float4*>(gsh);
        // one warp per k (8 warps, 8 k's each)
        for (int k = warp; k < K_CAPS; k += 8) {
            const float4* row4 = reinterpret_cast<const float4*>(base + (size_t)k * H_DIM);
            float s = 0.0f;
            #pragma unroll
            for (int i = lane; i < H_DIM / 4; i += 32) {
                float4 a = row4[i];
                float4 b = g4[i];
                s += a.x * b.x + a.y * b.y + a.z * b.z + a.w * b.w;
            }
            #pragma unroll
            for (int o = 16; o; o >>= 1) s += __shfl_down_sync(0xffffffffu, s, o);
            if (lane == 0) {
                float bn = g_b[c * K_CAPS + k] + s;
                g_b[c * K_CAPS + k] = bn;
                dsh[k] = bn;
            }
        }
        __syncthreads();
        // softmax over 64 logits (computed redundantly by all threads; smem broadcast)
        float m = -INFINITY;
        #pragma unroll
        for (int k = 0; k < K_CAPS; k++) m = fmaxf(m, dsh[k]);
        float sum = 0.0f;
        #pragma unroll
        for (int k = 0; k < K_CAPS; k++) sum += expf(dsh[k] - m);
        float inv = 1.0f / sum;
        __syncthreads();
        if (t < K_CAPS) dsh[t] = expf(dsh[t] - m) * inv;
        __syncthreads();
    }

    // weighted sum: thread t owns float4 column t (H/4 = 256 = blockDim)
    const float4* b4 = reinterpret_cast<const float4*>(base);
    float4 acc = make_float4(0.f, 0.f, 0.f, 0.f);
    #pragma unroll 8
    for (int k = 0; k < K_CAPS; k++) {
        float d = dsh[k];
        float4 v = b4[k * (H_DIM / 4) + t];
        acc.x += d * v.x; acc.y += d * v.y; acc.z += d * v.z; acc.w += d * v.w;
    }
    reinterpret_cast<float4*>(g_e)[c * (H_DIM / 4) + t] = acc;
}

// ---------------------------------------------------------------------------
// GEMM NT: chat[m,n] = sum_k e[m,k] * W[n,k]    (M=256, N=1024, K=1024)
// 32x64 block tile, BK=32, 128 threads, 4x4 microtile, float4 smem fragments.
__global__ void __launch_bounds__(128) gemm_nt_kernel(
        const float* __restrict__ W,
        const int* __restrict__ itern, int it) {
    if (it >= *itern) return;
    __shared__ float As[32][36];   // As[kk][m], stride 36 (16B aligned rows)
    __shared__ float Bs[32][68];   // Bs[kk][n], stride 68
    int m0 = blockIdx.x * 32;
    int n0 = blockIdx.y * 64;
    int t = threadIdx.x;
    int tx = t & 15;   // n group
    int ty = t >> 4;   // m group (0..7)
    float acc[4][4] = {};

    for (int k0 = 0; k0 < H_DIM; k0 += 32) {
        // A tile (32m x 32k): transpose into As[kk][m]
        {
            int r = t >> 2;
            int c4 = (t & 3) * 4;
            #pragma unroll
            for (int rep = 0; rep < 2; rep++) {
                int cc = c4 + rep * 16;
                float4 v = *reinterpret_cast<const float4*>(&g_e[(m0 + r) * H_DIM + k0 + cc]);
                As[cc + 0][r] = v.x; As[cc + 1][r] = v.y;
                As[cc + 2][r] = v.z; As[cc + 3][r] = v.w;
            }
        }
        // B tile: W rows are k-contiguous; transpose into Bs[kk][n]
        {
            int n  = t & 63;
            int kb = (t >> 6) * 16;    // {0,16}
            #pragma unroll
            for (int rep = 0; rep < 4; rep++) {
                int kk = kb + rep * 4;
                float4 v = *reinterpret_cast<const float4*>(&W[(size_t)(n0 + n) * H_DIM + k0 + kk]);
                Bs[kk + 0][n] = v.x; Bs[kk + 1][n] = v.y;
                Bs[kk + 2][n] = v.z; Bs[kk + 3][n] = v.w;
            }
        }
        __syncthreads();
        #pragma unroll
        for (int kk = 0; kk < 32; kk++) {
            float4 av = *reinterpret_cast<const float4*>(&As[kk][ty * 4]);
            float4 bv = *reinterpret_cast<const float4*>(&Bs[kk][tx * 4]);
            float a[4] = {av.x, av.y, av.z, av.w};
            float b[4] = {bv.x, bv.y, bv.z, bv.w};
            #pragma unroll
            for (int i = 0; i < 4; i++)
                #pragma unroll
                for (int j = 0; j < 4; j++)
                    acc[i][j] += a[i] * b[j];
        }
        __syncthreads();
    }
    #pragma unroll
    for (int i = 0; i < 4; i++) {
        float4 v = make_float4(acc[i][0], acc[i][1], acc[i][2], acc[i][3]);
        *reinterpret_cast<float4*>(&g_chat[(m0 + ty * 4 + i) * H_DIM + n0 + tx * 4]) = v;
    }
}

// ---------------------------------------------------------------------------
// squash: out[c,:] = (norm/(1+norm)) * chat[c,:] / sqrt(norm)
__global__ void __launch_bounds__(256) squash_kernel(
        float* __restrict__ out,
        const int* __restrict__ itern, int it) {
    if (it >= *itern) return;
    int c = blockIdx.x;
    int t = threadIdx.x;
    __shared__ float red[8];
    const float4* ch4 = reinterpret_cast<const float4*>(g_chat) + c * (H_DIM / 4);
    float4 v = ch4[t];
    float s = v.x * v.x + v.y * v.y + v.z * v.z + v.w * v.w;
    #pragma unroll
    for (int o = 16; o; o >>= 1) s += __shfl_down_sync(0xffffffffu, s, o);
    if ((t & 31) == 0) red[t >> 5] = s;
    __syncthreads();
    if (t < 32) {
        float r = (t < 8) ? red[t] : 0.0f;
        #pragma unroll
        for (int o = 4; o; o >>= 1) r += __shfl_down_sync(0xffffffffu, r, o);
        if (t == 0) red[0] = r;
    }
    __syncthreads();
    float norm = red[0];
    float scale = (norm / (1.0f + norm)) * rsqrtf(norm);
    float4 o4 = make_float4(scale * v.x, scale * v.y, scale * v.z, scale * v.w);
    reinterpret_cast<float4*>(out)[c * (H_DIM / 4) + t] = o4;
}

// ---------------------------------------------------------------------------
// GEMM NN: g[m,n] = sum_k c[m,k] * W[k,n]    (M=256, N=1024, K=1024)
// Only needed when another routing iteration follows.
__global__ void __launch_bounds__(128) gemm_nn_kernel(
        const float* __restrict__ W,
        const float* __restrict__ Cin,
        const int* __restrict__ itern, int it) {
    if (it + 1 >= *itern) return;
    __shared__ float As[32][36];   // As[kk][m]
    __shared__ float Bs[32][68];   // Bs[kk][n]
    int m0 = blockIdx.x * 32;
    int n0 = blockIdx.y * 64;
    int t = threadIdx.x;
    int tx = t & 15;
    int ty = t >> 4;
    float acc[4][4] = {};

    for (int k0 = 0; k0 < H_DIM; k0 += 32) {
        // A tile: Cin[m0+r][k0+..] → As[kk][m]
        {
            int r = t >> 2;
            int c4 = (t & 3) * 4;
            #pragma unroll
            for (int rep = 0; rep < 2; rep++) {
                int cc = c4 + rep * 16;
                float4 v = *reinterpret_cast<const float4*>(&Cin[(m0 + r) * H_DIM + k0 + cc]);
                As[cc + 0][r] = v.x; As[cc + 1][r] = v.y;
                As[cc + 2][r] = v.z; As[cc + 3][r] = v.w;
            }
        }
        // B tile: W[k0+kk][n0+..] n-contiguous → direct float4 stores
        {
            int kk = t >> 2;           // 0..31
            int nb = (t & 3) * 4;      // 0,4,8,12
            #pragma unroll
            for (int rep = 0; rep < 4; rep++) {
                int nn = nb + rep * 16;
                float4 v = *reinterpret_cast<const float4*>(&W[(size_t)(k0 + kk) * H_DIM + n0 + nn]);
                *reinterpret_cast<float4*>(&Bs[kk][nn]) = v;
            }
        }
        __syncthreads();
        #pragma unroll
        for (int kk = 0; kk < 32; kk++) {
            float4 av = *reinterpret_cast<const float4*>(&As[kk][ty * 4]);
            float4 bv = *reinterpret_cast<const float4*>(&Bs[kk][tx * 4]);
            float a[4] = {av.x, av.y, av.z, av.w};
            float b[4] = {bv.x, bv.y, bv.z, bv.w};
            #pragma unroll
            for (int i = 0; i < 4; i++)
                #pragma unroll
                for (int j = 0; j < 4; j++)
                    acc[i][j] += a[i] * b[j];
        }
        __syncthreads();
    }
    #pragma unroll
    for (int i = 0; i < 4; i++) {
        float4 v = make_float4(acc[i][0], acc[i][1], acc[i][2], acc[i][3]);
        *reinterpret_cast<float4*>(&g_g[(m0 + ty * 4 + i) * H_DIM + n0 + tx * 4]) = v;
    }
}

// ---------------------------------------------------------------------------
extern "C" void kernel_launch(void* const* d_in, const int* in_sizes, int n_in,
                              void* d_out, int out_size) {
    const float* enc   = (const float*)d_in[0];   // [C, K, H]
    const float* W     = (const float*)d_in[1];   // [H, H]
    const int*   itern = (const int*)d_in[2];     // scalar iter_routing
    float* out = (float*)d_out;                   // [C, H]

    dim3 gemm_grid(C_CAPS / 32, H_DIM / 64);      // (8, 16) = 128 blocks
    for (int it = 0; it < MAX_ITERS; it++) {
        route_kernel<<<C_CAPS, 256>>>(enc, itern, it);
        gemm_nt_kernel<<<gemm_grid, 128>>>(W, itern, it);
        squash_kernel<<<C_CAPS, 256>>>(out, itern, it);
        gemm_nn_kernel<<<gemm_grid, 128>>>(W, out, itern, it);
    }
}

// round 3
// speedup vs baseline: 1.4815x; 1.0440x over previous
#include <cuda_runtime.h>
#include <cuda_bf16.h>
#include <math.h>

#define C_CAPS 256
#define K_CAPS 64
#define H_DIM  1024
#define MAX_ITERS 4

// Scratch (device globals — no allocation allowed)
__device__ __align__(16) float g_b[C_CAPS * K_CAPS];      // routing logits  [C,K]
__device__ __align__(16) float g_e[C_CAPS * H_DIM];       // weighted enc sum [C,H]
__device__ __align__(16) float g_chat[C_CAPS * H_DIM];    // pre-squash      [C,H]
__device__ __align__(16) float g_g[C_CAPS * H_DIM];       // W^T c           [C,H]

// ---------------------------------------------------------------------------
// Fused routing step for capsule c (see R1 notes)
__global__ void __launch_bounds__(256) route_kernel(
        const float* __restrict__ enc,
        const int* __restrict__ itern, int it) {
    if (it >= *itern) return;
    int c = blockIdx.x;
    int t = threadIdx.x;
    int warp = t >> 5, lane = t & 31;
    __shared__ __align__(16) float gsh[H_DIM];
    __shared__ float dsh[K_CAPS];
    const float* base = enc + (size_t)c * K_CAPS * H_DIM;

    if (it == 0) {
        if (t < K_CAPS) { dsh[t] = 1.0f / (float)K_CAPS; g_b[c * K_CAPS + t] = 0.0f; }
        __syncthreads();
    } else {
        for (int h = t; h < H_DIM; h += 256) gsh[h] = g_g[c * H_DIM + h];
        __syncthreads();
        const float4* g4 = reinterpret_cast<const float4*>(gsh);
        for (int k = warp; k < K_CAPS; k += 8) {
            const float4* row4 = reinterpret_cast<const float4*>(base + (size_t)k * H_DIM);
            float s = 0.0f;
            #pragma unroll
            for (int i = lane; i < H_DIM / 4; i += 32) {
                float4 a = row4[i];
                float4 b = g4[i];
                s += a.x * b.x + a.y * b.y + a.z * b.z + a.w * b.w;
            }
            #pragma unroll
            for (int o = 16; o; o >>= 1) s += __shfl_down_sync(0xffffffffu, s, o);
            if (lane == 0) {
                float bn = g_b[c * K_CAPS + k] + s;
                g_b[c * K_CAPS + k] = bn;
                dsh[k] = bn;
            }
        }
        __syncthreads();
        float m = -INFINITY;
        #pragma unroll
        for (int k = 0; k < K_CAPS; k++) m = fmaxf(m, dsh[k]);
        float sum = 0.0f;
        #pragma unroll
        for (int k = 0; k < K_CAPS; k++) sum += expf(dsh[k] - m);
        float inv = 1.0f / sum;
        __syncthreads();
        if (t < K_CAPS) dsh[t] = expf(dsh[t] - m) * inv;
        __syncthreads();
    }

    const float4* b4 = reinterpret_cast<const float4*>(base);
    float4 acc = make_float4(0.f, 0.f, 0.f, 0.f);
    #pragma unroll 8
    for (int k = 0; k < K_CAPS; k++) {
        float d = dsh[k];
        float4 v = b4[k * (H_DIM / 4) + t];
        acc.x += d * v.x; acc.y += d * v.y; acc.z += d * v.z; acc.w += d * v.w;
    }
    reinterpret_cast<float4*>(g_e)[c * (H_DIM / 4) + t] = acc;
}

// ---------------------------------------------------------------------------
// Shared GEMM machinery: 32x64 tile, BK=32, 128 threads, 4x4 microtile,
// double-buffered SMEM + register-pipelined fragments.
#define GEMM_FMA16()                                                     \
    do {                                                                 \
        float a[4] = {a_cur.x, a_cur.y, a_cur.z, a_cur.w};               \
        float b[4] = {b_cur.x, b_cur.y, b_cur.z, b_cur.w};               \
        acc[0][0] += a[0]*b[0]; acc[0][1] += a[0]*b[1];                  \
        acc[0][2] += a[0]*b[2]; acc[0][3] += a[0]*b[3];                  \
        acc[1][0] += a[1]*b[0]; acc[1][1] += a[1]*b[1];                  \
        acc[1][2] += a[1]*b[2]; acc[1][3] += a[1]*b[3];                  \
        acc[2][0] += a[2]*b[0]; acc[2][1] += a[2]*b[1];                  \
        acc[2][2] += a[2]*b[2]; acc[2][3] += a[2]*b[3];                  \
        acc[3][0] += a[3]*b[0]; acc[3][1] += a[3]*b[1];                  \
        acc[3][2] += a[3]*b[2]; acc[3][3] += a[3]*b[3];                  \
    } while (0)

// GEMM NT: chat[m,n] = sum_k e[m,k] * W[n,k]    (M=256, N=1024, K=1024)
__global__ void __launch_bounds__(128) gemm_nt_kernel(
        const float* __restrict__ W,
        const int* __restrict__ itern, int it) {
    if (it >= *itern) return;
    __shared__ float As[2][32][36];   // As[buf][kk][m]
    __shared__ float Bs[2][32][68];   // Bs[buf][kk][n]
    int m0 = blockIdx.x * 32;
    int n0 = blockIdx.y * 64;
    int t = threadIdx.x;
    int tx = t & 15;
    int ty = t >> 4;
    float acc[4][4] = {};

    // load-index precompute
    int ar  = t >> 2;                 // A row (m) 0..31
    int ac4 = (t & 3) * 4;            // A k sub-col
    int bn  = t & 63;                 // B n row 0..63
    int bkb = (t >> 6) * 16;          // B k base {0,16}

    const float* Ag = &g_e[(m0 + ar) * H_DIM + ac4];
    const float* Bg = &W[(size_t)(n0 + bn) * H_DIM + bkb];

    float4 aS[2], bS[4];
    // prologue: tile 0 loads
    #pragma unroll
    for (int r = 0; r < 2; r++) aS[r] = *reinterpret_cast<const float4*>(Ag + r * 16);
    #pragma unroll
    for (int r = 0; r < 4; r++) bS[r] = *reinterpret_cast<const float4*>(Bg + r * 4);
    #pragma unroll
    for (int r = 0; r < 2; r++) {
        int cc = ac4 + r * 16;
        As[0][cc + 0][ar] = aS[r].x; As[0][cc + 1][ar] = aS[r].y;
        As[0][cc + 2][ar] = aS[r].z; As[0][cc + 3][ar] = aS[r].w;
    }
    #pragma unroll
    for (int r = 0; r < 4; r++) {
        int kk = bkb + r * 4;
        Bs[0][kk + 0][bn] = bS[r].x; Bs[0][kk + 1][bn] = bS[r].y;
        Bs[0][kk + 2][bn] = bS[r].z; Bs[0][kk + 3][bn] = bS[r].w;
    }
    __syncthreads();

    for (int s = 0; s < 32; s++) {
        int cur = s & 1;
        int nxt = cur ^ 1;
        if (s + 1 < 32) {
            int k0n = (s + 1) * 32;
            #pragma unroll
            for (int r = 0; r < 2; r++) aS[r] = *reinterpret_cast<const float4*>(Ag + k0n + r * 16);
            #pragma unroll
            for (int r = 0; r < 4; r++) bS[r] = *reinterpret_cast<const float4*>(Bg + k0n + r * 4);
        }
        // compute on cur with fragment pipelining
        float4 a_cur = *reinterpret_cast<const float4*>(&As[cur][0][ty * 4]);
        float4 b_cur = *reinterpret_cast<const float4*>(&Bs[cur][0][tx * 4]);
        #pragma unroll
        for (int kk = 0; kk < 32; kk++) {
            float4 a_nxt, b_nxt;
            if (kk < 31) {
                a_nxt = *reinterpret_cast<const float4*>(&As[cur][kk + 1][ty * 4]);
                b_nxt = *reinterpret_cast<const float4*>(&Bs[cur][kk + 1][tx * 4]);
            }
            GEMM_FMA16();
            if (kk < 31) { a_cur = a_nxt; b_cur = b_nxt; }
        }
        if (s + 1 < 32) {
            #pragma unroll
            for (int r = 0; r < 2; r++) {
                int cc = ac4 + r * 16;
                As[nxt][cc + 0][ar] = aS[r].x; As[nxt][cc + 1][ar] = aS[r].y;
                As[nxt][cc + 2][ar] = aS[r].z; As[nxt][cc + 3][ar] = aS[r].w;
            }
            #pragma unroll
            for (int r = 0; r < 4; r++) {
                int kk = bkb + r * 4;
                Bs[nxt][kk + 0][bn] = bS[r].x; Bs[nxt][kk + 1][bn] = bS[r].y;
                Bs[nxt][kk + 2][bn] = bS[r].z; Bs[nxt][kk + 3][bn] = bS[r].w;
            }
            __syncthreads();
        }
    }
    #pragma unroll
    for (int i = 0; i < 4; i++) {
        float4 v = make_float4(acc[i][0], acc[i][1], acc[i][2], acc[i][3]);
        *reinterpret_cast<float4*>(&g_chat[(m0 + ty * 4 + i) * H_DIM + n0 + tx * 4]) = v;
    }
}

// GEMM NN: g[m,n] = sum_k c[m,k] * W[k,n]; only if another iteration follows.
__global__ void __launch_bounds__(128) gemm_nn_kernel(
        const float* __restrict__ W,
        const float* __restrict__ Cin,
        const int* __restrict__ itern, int it) {
    if (it + 1 >= *itern) return;
    __shared__ float As[2][32][36];   // As[buf][kk][m]
    __shared__ float Bs[2][32][68];   // Bs[buf][kk][n]
    int m0 = blockIdx.x * 32;
    int n0 = blockIdx.y * 64;
    int t = threadIdx.x;
    int tx = t & 15;
    int ty = t >> 4;
    float acc[4][4] = {};

    int ar  = t >> 2;
    int ac4 = (t & 3) * 4;
    int bkk = t >> 2;                 // B k row 0..31
    int bnb = (t & 3) * 4;            // B n sub-col

    const float* Ag = &Cin[(m0 + ar) * H_DIM + ac4];
    const float* Bg = &W[(size_t)bkk * H_DIM + n0 + bnb];

    float4 aS[2], bS[4];
    #pragma unroll
    for (int r = 0; r < 2; r++) aS[r] = *reinterpret_cast<const float4*>(Ag + r * 16);
    #pragma unroll
    for (int r = 0; r < 4; r++) bS[r] = *reinterpret_cast<const float4*>(Bg + r * 16);
    #pragma unroll
    for (int r = 0; r < 2; r++) {
        int cc = ac4 + r * 16;
        As[0][cc + 0][ar] = aS[r].x; As[0][cc + 1][ar] = aS[r].y;
        As[0][cc + 2][ar] = aS[r].z; As[0][cc + 3][ar] = aS[r].w;
    }
    #pragma unroll
    for (int r = 0; r < 4; r++)
        *reinterpret_cast<float4*>(&Bs[0][bkk][bnb + r * 16]) = bS[r];
    __syncthreads();

    for (int s = 0; s < 32; s++) {
        int cur = s & 1;
        int nxt = cur ^ 1;
        if (s + 1 < 32) {
            int k0n = (s + 1) * 32;
            #pragma unroll
            for (int r = 0; r < 2; r++) aS[r] = *reinterpret_cast<const float4*>(Ag + k0n + r * 16);
            #pragma unroll
            for (int r = 0; r < 4; r++) bS[r] = *reinterpret_cast<const float4*>(Bg + (size_t)k0n * H_DIM + r * 16);
        }
        float4 a_cur = *reinterpret_cast<const float4*>(&As[cur][0][ty * 4]);
        float4 b_cur = *reinterpret_cast<const float4*>(&Bs[cur][0][tx * 4]);
        #pragma unroll
        for (int kk = 0; kk < 32; kk++) {
            float4 a_nxt, b_nxt;
            if (kk < 31) {
                a_nxt = *reinterpret_cast<const float4*>(&As[cur][kk + 1][ty * 4]);
                b_nxt = *reinterpret_cast<const float4*>(&Bs[cur][kk + 1][tx * 4]);
            }
            GEMM_FMA16();
            if (kk < 31) { a_cur = a_nxt; b_cur = b_nxt; }
        }
        if (s + 1 < 32) {
            #pragma unroll
            for (int r = 0; r < 2; r++) {
                int cc = ac4 + r * 16;
                As[nxt][cc + 0][ar] = aS[r].x; As[nxt][cc + 1][ar] = aS[r].y;
                As[nxt][cc + 2][ar] = aS[r].z; As[nxt][cc + 3][ar] = aS[r].w;
            }
            #pragma unroll
            for (int r = 0; r < 4; r++)
                *reinterpret_cast<float4*>(&Bs[nxt][bkk][bnb + r * 16]) = bS[r];
            __syncthreads();
        }
    }
    #pragma unroll
    for (int i = 0; i < 4; i++) {
        float4 v = make_float4(acc[i][0], acc[i][1], acc[i][2], acc[i][3]);
        *reinterpret_cast<float4*>(&g_g[(m0 + ty * 4 + i) * H_DIM + n0 + tx * 4]) = v;
    }
}

// ---------------------------------------------------------------------------
// squash: out[c,:] = (norm/(1+norm)) * chat[c,:] / sqrt(norm)
__global__ void __launch_bounds__(256) squash_kernel(
        float* __restrict__ out,
        const int* __restrict__ itern, int it) {
    if (it >= *itern) return;
    int c = blockIdx.x;
    int t = threadIdx.x;
    __shared__ float red[8];
    const float4* ch4 = reinterpret_cast<const float4*>(g_chat) + c * (H_DIM / 4);
    float4 v = ch4[t];
    float s = v.x * v.x + v.y * v.y + v.z * v.z + v.w * v.w;
    #pragma unroll
    for (int o = 16; o; o >>= 1) s += __shfl_down_sync(0xffffffffu, s, o);
    if ((t & 31) == 0) red[t >> 5] = s;
    __syncthreads();
    if (t < 32) {
        float r = (t < 8) ? red[t] : 0.0f;
        #pragma unroll
        for (int o = 4; o; o >>= 1) r += __shfl_down_sync(0xffffffffu, r, o);
        if (t == 0) red[0] = r;
    }
    __syncthreads();
    float norm = red[0];
    float scale = (norm / (1.0f + norm)) * rsqrtf(norm);
    float4 o4 = make_float4(scale * v.x, scale * v.y, scale * v.z, scale * v.w);
    reinterpret_cast<float4*>(out)[c * (H_DIM / 4) + t] = o4;
}

// ---------------------------------------------------------------------------
extern "C" void kernel_launch(void* const* d_in, const int* in_sizes, int n_in,
                              void* d_out, int out_size) {
    const float* enc   = (const float*)d_in[0];   // [C, K, H]
    const float* W     = (const float*)d_in[1];   // [H, H]
    const int*   itern = (const int*)d_in[2];     // scalar iter_routing
    float* out = (float*)d_out;                   // [C, H]

    dim3 gemm_grid(C_CAPS / 32, H_DIM / 64);      // (8, 16) = 128 blocks
    for (int it = 0; it < MAX_ITERS; it++) {
        route_kernel<<<C_CAPS, 256>>>(enc, itern, it);
        gemm_nt_kernel<<<gemm_grid, 128>>>(W, itern, it);
        squash_kernel<<<C_CAPS, 256>>>(out, itern, it);
        gemm_nn_kernel<<<gemm_grid, 128>>>(W, out, itern, it);
    }
}

// round 4
// speedup vs baseline: 1.9517x; 1.3174x over previous
#include <cuda_runtime.h>
#include <cuda_bf16.h>
#include <math.h>

#define C_CAPS 256
#define K_CAPS 64
#define H_DIM  1024
#define MAX_ITERS 4
#define KSPLIT 4
#define KSLICE (H_DIM / KSPLIT)   // 256

// Scratch (device globals — no allocation allowed)
__device__ __align__(16) float g_b[C_CAPS * K_CAPS];                    // logits [C,K]
__device__ __align__(16) float g_e[C_CAPS * H_DIM];                     // weighted enc sum
__device__ __align__(16) float g_chat_p[KSPLIT][C_CAPS * H_DIM];        // partial pre-squash
__device__ __align__(16) float g_g_p[KSPLIT][C_CAPS * H_DIM];           // partial W^T c

// ---------------------------------------------------------------------------
// Fused routing step for capsule c:
//   (it>0)  g = sum_z g_g_p[z];  b[c,k] += dot(enc[c,k,:], g);  d = softmax(b)
//   (it==0) b = 0; d = 1/K
//   e[c,:] = sum_k d[k] * enc[c,k,:]
__global__ void __launch_bounds__(256) route_kernel(
        const float* __restrict__ enc,
        const int* __restrict__ itern, int it) {
    if (it >= *itern) return;
    int c = blockIdx.x;
    int t = threadIdx.x;
    int warp = t >> 5, lane = t & 31;
    __shared__ __align__(16) float gsh[H_DIM];
    __shared__ float dsh[K_CAPS];
    const float* base = enc + (size_t)c * K_CAPS * H_DIM;

    if (it == 0) {
        if (t < K_CAPS) { dsh[t] = 1.0f / (float)K_CAPS; g_b[c * K_CAPS + t] = 0.0f; }
        __syncthreads();
    } else {
        for (int h = t; h < H_DIM; h += 256) {
            float s = g_g_p[0][c * H_DIM + h];
            #pragma unroll
            for (int z = 1; z < KSPLIT; z++) s += g_g_p[z][c * H_DIM + h];
            gsh[h] = s;
        }
        __syncthreads();
        const float4* g4 = reinterpret_cast<const float4*>(gsh);
        for (int k = warp; k < K_CAPS; k += 8) {
            const float4* row4 = reinterpret_cast<const float4*>(base + (size_t)k * H_DIM);
            float s = 0.0f;
            #pragma unroll
            for (int i = lane; i < H_DIM / 4; i += 32) {
                float4 a = row4[i];
                float4 b = g4[i];
                s += a.x * b.x + a.y * b.y + a.z * b.z + a.w * b.w;
            }
            #pragma unroll
            for (int o = 16; o; o >>= 1) s += __shfl_down_sync(0xffffffffu, s, o);
            if (lane == 0) {
                float bn = g_b[c * K_CAPS + k] + s;
                g_b[c * K_CAPS + k] = bn;
                dsh[k] = bn;
            }
        }
        __syncthreads();
        float m = -INFINITY;
        #pragma unroll
        for (int k = 0; k < K_CAPS; k++) m = fmaxf(m, dsh[k]);
        float sum = 0.0f;
        #pragma unroll
        for (int k = 0; k < K_CAPS; k++) sum += expf(dsh[k] - m);
        float inv = 1.0f / sum;
        __syncthreads();
        if (t < K_CAPS) dsh[t] = expf(dsh[t] - m) * inv;
        __syncthreads();
    }

    const float4* b4 = reinterpret_cast<const float4*>(base);
    float4 acc = make_float4(0.f, 0.f, 0.f, 0.f);
    #pragma unroll 8
    for (int k = 0; k < K_CAPS; k++) {
        float d = dsh[k];
        float4 v = b4[k * (H_DIM / 4) + t];
        acc.x += d * v.x; acc.y += d * v.y; acc.z += d * v.z; acc.w += d * v.w;
    }
    reinterpret_cast<float4*>(g_e)[c * (H_DIM / 4) + t] = acc;
}

// ---------------------------------------------------------------------------
// GEMM core: 32x64 tile, BK=32, 128 threads, 4x4 microtile, K-split by blockIdx.z.
#define GEMM_FMA16()                                                     \
    do {                                                                 \
        float a[4] = {a_cur.x, a_cur.y, a_cur.z, a_cur.w};               \
        float b[4] = {b_cur.x, b_cur.y, b_cur.z, b_cur.w};               \
        acc[0][0] += a[0]*b[0]; acc[0][1] += a[0]*b[1];                  \
        acc[0][2] += a[0]*b[2]; acc[0][3] += a[0]*b[3];                  \
        acc[1][0] += a[1]*b[0]; acc[1][1] += a[1]*b[1];                  \
        acc[1][2] += a[1]*b[2]; acc[1][3] += a[1]*b[3];                  \
        acc[2][0] += a[2]*b[0]; acc[2][1] += a[2]*b[1];                  \
        acc[2][2] += a[2]*b[2]; acc[2][3] += a[2]*b[3];                  \
        acc[3][0] += a[3]*b[0]; acc[3][1] += a[3]*b[1];                  \
        acc[3][2] += a[3]*b[2]; acc[3][3] += a[3]*b[3];                  \
    } while (0)

#define NSTEPS (KSLICE / 32)    // 8 k0-steps per slice

// GEMM NT: chat_p[z][m,n] = sum_{k in slice z} e[m,k] * W[n,k]
__global__ void __launch_bounds__(128) gemm_nt_kernel(
        const float* __restrict__ W,
        const int* __restrict__ itern, int it) {
    if (it >= *itern) return;
    __shared__ float As[2][32][36];
    __shared__ float Bs[2][32][68];
    int m0 = blockIdx.x * 32;
    int n0 = blockIdx.y * 64;
    int kz = blockIdx.z * KSLICE;
    int t = threadIdx.x;
    int tx = t & 15;
    int ty = t >> 4;
    float acc[4][4] = {};

    int ar  = t >> 2;
    int ac4 = (t & 3) * 4;
    int bn  = t & 63;
    int bkb = (t >> 6) * 16;

    const float* Ag = &g_e[(m0 + ar) * H_DIM + kz + ac4];
    const float* Bg = &W[(size_t)(n0 + bn) * H_DIM + kz + bkb];

    float4 aS[2], bS[4];
    #pragma unroll
    for (int r = 0; r < 2; r++) aS[r] = *reinterpret_cast<const float4*>(Ag + r * 16);
    #pragma unroll
    for (int r = 0; r < 4; r++) bS[r] = *reinterpret_cast<const float4*>(Bg + r * 4);
    #pragma unroll
    for (int r = 0; r < 2; r++) {
        int cc = ac4 + r * 16;
        As[0][cc + 0][ar] = aS[r].x; As[0][cc + 1][ar] = aS[r].y;
        As[0][cc + 2][ar] = aS[r].z; As[0][cc + 3][ar] = aS[r].w;
    }
    #pragma unroll
    for (int r = 0; r < 4; r++) {
        int kk = bkb + r * 4;
        Bs[0][kk + 0][bn] = bS[r].x; Bs[0][kk + 1][bn] = bS[r].y;
        Bs[0][kk + 2][bn] = bS[r].z; Bs[0][kk + 3][bn] = bS[r].w;
    }
    __syncthreads();

    for (int s = 0; s < NSTEPS; s++) {
        int cur = s & 1;
        int nxt = cur ^ 1;
        if (s + 1 < NSTEPS) {
            int k0n = (s + 1) * 32;
            #pragma unroll
            for (int r = 0; r < 2; r++) aS[r] = *reinterpret_cast<const float4*>(Ag + k0n + r * 16);
            #pragma unroll
            for (int r = 0; r < 4; r++) bS[r] = *reinterpret_cast<const float4*>(Bg + k0n + r * 4);
        }
        float4 a_cur = *reinterpret_cast<const float4*>(&As[cur][0][ty * 4]);
        float4 b_cur = *reinterpret_cast<const float4*>(&Bs[cur][0][tx * 4]);
        #pragma unroll
        for (int kk = 0; kk < 32; kk++) {
            float4 a_nxt, b_nxt;
            if (kk < 31) {
                a_nxt = *reinterpret_cast<const float4*>(&As[cur][kk + 1][ty * 4]);
                b_nxt = *reinterpret_cast<const float4*>(&Bs[cur][kk + 1][tx * 4]);
            }
            GEMM_FMA16();
            if (kk < 31) { a_cur = a_nxt; b_cur = b_nxt; }
        }
        if (s + 1 < NSTEPS) {
            #pragma unroll
            for (int r = 0; r < 2; r++) {
                int cc = ac4 + r * 16;
                As[nxt][cc + 0][ar] = aS[r].x; As[nxt][cc + 1][ar] = aS[r].y;
                As[nxt][cc + 2][ar] = aS[r].z; As[nxt][cc + 3][ar] = aS[r].w;
            }
            #pragma unroll
            for (int r = 0; r < 4; r++) {
                int kk = bkb + r * 4;
                Bs[nxt][kk + 0][bn] = bS[r].x; Bs[nxt][kk + 1][bn] = bS[r].y;
                Bs[nxt][kk + 2][bn] = bS[r].z; Bs[nxt][kk + 3][bn] = bS[r].w;
            }
            __syncthreads();
        }
    }
    float* outp = g_chat_p[blockIdx.z];
    #pragma unroll
    for (int i = 0; i < 4; i++) {
        float4 v = make_float4(acc[i][0], acc[i][1], acc[i][2], acc[i][3]);
        *reinterpret_cast<float4*>(&outp[(m0 + ty * 4 + i) * H_DIM + n0 + tx * 4]) = v;
    }
}

// GEMM NN: g_p[z][m,n] = sum_{k in slice z} c[m,k] * W[k,n]; only if another iter follows.
__global__ void __launch_bounds__(128) gemm_nn_kernel(
        const float* __restrict__ W,
        const float* __restrict__ Cin,
        const int* __restrict__ itern, int it) {
    if (it + 1 >= *itern) return;
    __shared__ float As[2][32][36];
    __shared__ float Bs[2][32][68];
    int m0 = blockIdx.x * 32;
    int n0 = blockIdx.y * 64;
    int kz = blockIdx.z * KSLICE;
    int t = threadIdx.x;
    int tx = t & 15;
    int ty = t >> 4;
    float acc[4][4] = {};

    int ar  = t >> 2;
    int ac4 = (t & 3) * 4;
    int bkk = t >> 2;
    int bnb = (t & 3) * 4;

    const float* Ag = &Cin[(m0 + ar) * H_DIM + kz + ac4];
    const float* Bg = &W[(size_t)(kz + bkk) * H_DIM + n0 + bnb];

    float4 aS[2], bS[4];
    #pragma unroll
    for (int r = 0; r < 2; r++) aS[r] = *reinterpret_cast<const float4*>(Ag + r * 16);
    #pragma unroll
    for (int r = 0; r < 4; r++) bS[r] = *reinterpret_cast<const float4*>(Bg + r * 16);
    #pragma unroll
    for (int r = 0; r < 2; r++) {
        int cc = ac4 + r * 16;
        As[0][cc + 0][ar] = aS[r].x; As[0][cc + 1][ar] = aS[r].y;
        As[0][cc + 2][ar] = aS[r].z; As[0][cc + 3][ar] = aS[r].w;
    }
    #pragma unroll
    for (int r = 0; r < 4; r++)
        *reinterpret_cast<float4*>(&Bs[0][bkk][bnb + r * 16]) = bS[r];
    __syncthreads();

    for (int s = 0; s < NSTEPS; s++) {
        int cur = s & 1;
        int nxt = cur ^ 1;
        if (s + 1 < NSTEPS) {
            int k0n = (s + 1) * 32;
            #pragma unroll
            for (int r = 0; r < 2; r++) aS[r] = *reinterpret_cast<const float4*>(Ag + k0n + r * 16);
            #pragma unroll
            for (int r = 0; r < 4; r++) bS[r] = *reinterpret_cast<const float4*>(Bg + (size_t)k0n * H_DIM + r * 16);
        }
        float4 a_cur = *reinterpret_cast<const float4*>(&As[cur][0][ty * 4]);
        float4 b_cur = *reinterpret_cast<const float4*>(&Bs[cur][0][tx * 4]);
        #pragma unroll
        for (int kk = 0; kk < 32; kk++) {
            float4 a_nxt, b_nxt;
            if (kk < 31) {
                a_nxt = *reinterpret_cast<const float4*>(&As[cur][kk + 1][ty * 4]);
                b_nxt = *reinterpret_cast<const float4*>(&Bs[cur][kk + 1][tx * 4]);
            }
            GEMM_FMA16();
            if (kk < 31) { a_cur = a_nxt; b_cur = b_nxt; }
        }
        if (s + 1 < NSTEPS) {
            #pragma unroll
            for (int r = 0; r < 2; r++) {
                int cc = ac4 + r * 16;
                As[nxt][cc + 0][ar] = aS[r].x; As[nxt][cc + 1][ar] = aS[r].y;
                As[nxt][cc + 2][ar] = aS[r].z; As[nxt][cc + 3][ar] = aS[r].w;
            }
            #pragma unroll
            for (int r = 0; r < 4; r++)
                *reinterpret_cast<float4*>(&Bs[nxt][bkk][bnb + r * 16]) = bS[r];
            __syncthreads();
        }
    }
    float* outp = g_g_p[blockIdx.z];
    #pragma unroll
    for (int i = 0; i < 4; i++) {
        float4 v = make_float4(acc[i][0], acc[i][1], acc[i][2], acc[i][3]);
        *reinterpret_cast<float4*>(&outp[(m0 + ty * 4 + i) * H_DIM + n0 + tx * 4]) = v;
    }
}

// ---------------------------------------------------------------------------
// squash: chat = sum_z chat_p[z]; out = (norm/(1+norm)) * chat / sqrt(norm)
__global__ void __launch_bounds__(256) squash_kernel(
        float* __restrict__ out,
        const int* __restrict__ itern, int it) {
    if (it >= *itern) return;
    int c = blockIdx.x;
    int t = threadIdx.x;
    __shared__ float red[8];
    int idx = c * (H_DIM / 4) + t;
    float4 v = reinterpret_cast<const float4*>(g_chat_p[0])[idx];
    #pragma unroll
    for (int z = 1; z < KSPLIT; z++) {
        float4 p = reinterpret_cast<const float4*>(g_chat_p[z])[idx];
        v.x += p.x; v.y += p.y; v.z += p.z; v.w += p.w;
    }
    float s = v.x * v.x + v.y * v.y + v.z * v.z + v.w * v.w;
    #pragma unroll
    for (int o = 16; o; o >>= 1) s += __shfl_down_sync(0xffffffffu, s, o);
    if ((t & 31) == 0) red[t >> 5] = s;
    __syncthreads();
    if (t < 32) {
        float r = (t < 8) ? red[t] : 0.0f;
        #pragma unroll
        for (int o = 4; o; o >>= 1) r += __shfl_down_sync(0xffffffffu, r, o);
        if (t == 0) red[0] = r;
    }
    __syncthreads();
    float norm = red[0];
    float scale = (norm / (1.0f + norm)) * rsqrtf(norm);
    float4 o4 = make_float4(scale * v.x, scale * v.y, scale * v.z, scale * v.w);
    reinterpret_cast<float4*>(out)[idx] = o4;
}

// ---------------------------------------------------------------------------
extern "C" void kernel_launch(void* const* d_in, const int* in_sizes, int n_in,
                              void* d_out, int out_size) {
    const float* enc   = (const float*)d_in[0];   // [C, K, H]
    const float* W     = (const float*)d_in[1];   // [H, H]
    const int*   itern = (const int*)d_in[2];     // scalar iter_routing
    float* out = (float*)d_out;                   // [C, H]

    dim3 gemm_grid(C_CAPS / 32, H_DIM / 64, KSPLIT);   // (8, 16, 4) = 512 blocks
    for (int it = 0; it < MAX_ITERS; it++) {
        route_kernel<<<C_CAPS, 256>>>(enc, itern, it);
        gemm_nt_kernel<<<gemm_grid, 128>>>(W, itern, it);
        squash_kernel<<<C_CAPS, 256>>>(out, itern, it);
        gemm_nn_kernel<<<gemm_grid, 128>>>(W, out, itern, it);
    }
}

// round 5
// speedup vs baseline: 2.1935x; 1.1239x over previous
#include <cuda_runtime.h>
#include <cuda_bf16.h>
#include <math.h>

#define C_CAPS 256
#define K_CAPS 64
#define H_DIM  1024
#define MAX_ITERS 4
#define KSPLIT 8
#define KSLICE (H_DIM / KSPLIT)   // 128
#define NSTEPS (KSLICE / 32)      // 4

// Scratch (device globals — no allocation allowed)
__device__ __align__(16) float g_b[C_CAPS * K_CAPS];                    // logits [C,K]
__device__ __align__(16) float g_e[C_CAPS * H_DIM];                     // weighted enc sum
__device__ __align__(16) float g_chat_p[KSPLIT][C_CAPS * H_DIM];        // partial pre-squash
__device__ __align__(16) float g_g_p[KSPLIT][C_CAPS * H_DIM];           // partial W^T c

// ---------------------------------------------------------------------------
// Fused routing step for capsule c
__global__ void __launch_bounds__(256) route_kernel(
        const float* __restrict__ enc,
        const int* __restrict__ itern, int it) {
    if (it >= *itern) return;
    int c = blockIdx.x;
    int t = threadIdx.x;
    int warp = t >> 5, lane = t & 31;
    __shared__ __align__(16) float gsh[H_DIM];
    __shared__ float dsh[K_CAPS];
    const float* base = enc + (size_t)c * K_CAPS * H_DIM;

    if (it == 0) {
        if (t < K_CAPS) { dsh[t] = 1.0f / (float)K_CAPS; g_b[c * K_CAPS + t] = 0.0f; }
        __syncthreads();
    } else {
        for (int h = t; h < H_DIM; h += 256) {
            float s = g_g_p[0][c * H_DIM + h];
            #pragma unroll
            for (int z = 1; z < KSPLIT; z++) s += g_g_p[z][c * H_DIM + h];
            gsh[h] = s;
        }
        __syncthreads();
        const float4* g4 = reinterpret_cast<const float4*>(gsh);
        for (int k = warp; k < K_CAPS; k += 8) {
            const float4* row4 = reinterpret_cast<const float4*>(base + (size_t)k * H_DIM);
            float s = 0.0f;
            #pragma unroll
            for (int i = lane; i < H_DIM / 4; i += 32) {
                float4 a = row4[i];
                float4 b = g4[i];
                s += a.x * b.x + a.y * b.y + a.z * b.z + a.w * b.w;
            }
            #pragma unroll
            for (int o = 16; o; o >>= 1) s += __shfl_down_sync(0xffffffffu, s, o);
            if (lane == 0) {
                float bn = g_b[c * K_CAPS + k] + s;
                g_b[c * K_CAPS + k] = bn;
                dsh[k] = bn;
            }
        }
        __syncthreads();
        float m = -INFINITY;
        #pragma unroll
        for (int k = 0; k < K_CAPS; k++) m = fmaxf(m, dsh[k]);
        float sum = 0.0f;
        #pragma unroll
        for (int k = 0; k < K_CAPS; k++) sum += expf(dsh[k] - m);
        float inv = 1.0f / sum;
        __syncthreads();
        if (t < K_CAPS) dsh[t] = expf(dsh[t] - m) * inv;
        __syncthreads();
    }

    const float4* b4 = reinterpret_cast<const float4*>(base);
    float4 acc = make_float4(0.f, 0.f, 0.f, 0.f);
    #pragma unroll 8
    for (int k = 0; k < K_CAPS; k++) {
        float d = dsh[k];
        float4 v = b4[k * (H_DIM / 4) + t];
        acc.x += d * v.x; acc.y += d * v.y; acc.z += d * v.z; acc.w += d * v.w;
    }
    reinterpret_cast<float4*>(g_e)[c * (H_DIM / 4) + t] = acc;
}

// ---------------------------------------------------------------------------
// GEMM core: 64x64 tile, BK=32, 128 threads, 8x4 microtile, K-split z.
// Per kk: 3 LDS.128 + 32 FFMA -> fma-bound (crossbar at ~75% of fma demand).
#define GEMM_FMA32()                                                        \
    do {                                                                    \
        float a[8] = {a0.x, a0.y, a0.z, a0.w, a1.x, a1.y, a1.z, a1.w};      \
        float b[4] = {bf.x, bf.y, bf.z, bf.w};                              \
        _Pragma("unroll")                                                   \
        for (int i = 0; i < 8; i++) {                                       \
            acc[i][0] += a[i] * b[0];                                       \
            acc[i][1] += a[i] * b[1];                                       \
            acc[i][2] += a[i] * b[2];                                       \
            acc[i][3] += a[i] * b[3];                                       \
        }                                                                   \
    } while (0)

// GEMM NT: chat_p[z][m,n] = sum_{k in slice z} e[m,k] * W[n,k]
__global__ void __launch_bounds__(128) gemm_nt_kernel(
        const float* __restrict__ W,
        const int* __restrict__ itern, int it) {
    if (it >= *itern) return;
    __shared__ float As[2][32][68];   // As[buf][kk][m]
    __shared__ float Bs[2][32][68];   // Bs[buf][kk][n]
    int m0 = blockIdx.x * 64;
    int n0 = blockIdx.y * 64;
    int kz = blockIdx.z * KSLICE;
    int t = threadIdx.x;
    int tx = t & 15;      // n group
    int ty = t >> 4;      // m group (0..7)
    float acc[8][4] = {};

    int ar = t >> 1;             // 0..63 (A row / B n-row)
    int ac = (t & 1) * 16;       // k sub-base {0,16}

    const float* Ag = &g_e[(m0 + ar) * H_DIM + kz + ac];
    const float* Bg = &W[(size_t)(n0 + ar) * H_DIM + kz + ac];

    float4 aS[4], bS[4];
    #pragma unroll
    for (int j = 0; j < 4; j++) {
        aS[j] = *reinterpret_cast<const float4*>(Ag + j * 4);
        bS[j] = *reinterpret_cast<const float4*>(Bg + j * 4);
    }
    #pragma unroll
    for (int j = 0; j < 4; j++) {
        int cc = ac + j * 4;
        As[0][cc + 0][ar] = aS[j].x; As[0][cc + 1][ar] = aS[j].y;
        As[0][cc + 2][ar] = aS[j].z; As[0][cc + 3][ar] = aS[j].w;
        Bs[0][cc + 0][ar] = bS[j].x; Bs[0][cc + 1][ar] = bS[j].y;
        Bs[0][cc + 2][ar] = bS[j].z; Bs[0][cc + 3][ar] = bS[j].w;
    }
    __syncthreads();

    for (int s = 0; s < NSTEPS; s++) {
        int cur = s & 1;
        int nxt = cur ^ 1;
        if (s + 1 < NSTEPS) {
            int k0n = (s + 1) * 32;
            #pragma unroll
            for (int j = 0; j < 4; j++) {
                aS[j] = *reinterpret_cast<const float4*>(Ag + k0n + j * 4);
                bS[j] = *reinterpret_cast<const float4*>(Bg + k0n + j * 4);
            }
        }
        float4 a0 = *reinterpret_cast<const float4*>(&As[cur][0][ty * 8]);
        float4 a1 = *reinterpret_cast<const float4*>(&As[cur][0][ty * 8 + 4]);
        float4 bf = *reinterpret_cast<const float4*>(&Bs[cur][0][tx * 4]);
        #pragma unroll
        for (int kk = 0; kk < 32; kk++) {
            float4 a0n, a1n, bfn;
            if (kk < 31) {
                a0n = *reinterpret_cast<const float4*>(&As[cur][kk + 1][ty * 8]);
                a1n = *reinterpret_cast<const float4*>(&As[cur][kk + 1][ty * 8 + 4]);
                bfn = *reinterpret_cast<const float4*>(&Bs[cur][kk + 1][tx * 4]);
            }
            GEMM_FMA32();
            if (kk < 31) { a0 = a0n; a1 = a1n; bf = bfn; }
        }
        if (s + 1 < NSTEPS) {
            #pragma unroll
            for (int j = 0; j < 4; j++) {
                int cc = ac + j * 4;
                As[nxt][cc + 0][ar] = aS[j].x; As[nxt][cc + 1][ar] = aS[j].y;
                As[nxt][cc + 2][ar] = aS[j].z; As[nxt][cc + 3][ar] = aS[j].w;
                Bs[nxt][cc + 0][ar] = bS[j].x; Bs[nxt][cc + 1][ar] = bS[j].y;
                Bs[nxt][cc + 2][ar] = bS[j].z; Bs[nxt][cc + 3][ar] = bS[j].w;
            }
            __syncthreads();
        }
    }
    float* outp = g_chat_p[blockIdx.z];
    #pragma unroll
    for (int i = 0; i < 8; i++) {
        float4 v = make_float4(acc[i][0], acc[i][1], acc[i][2], acc[i][3]);
        *reinterpret_cast<float4*>(&outp[(m0 + ty * 8 + i) * H_DIM + n0 + tx * 4]) = v;
    }
}

// GEMM NN: g_p[z][m,n] = sum_{k in slice z} c[m,k] * W[k,n]; only if another iter follows.
__global__ void __launch_bounds__(128) gemm_nn_kernel(
        const float* __restrict__ W,
        const float* __restrict__ Cin,
        const int* __restrict__ itern, int it) {
    if (it + 1 >= *itern) return;
    __shared__ float As[2][32][68];
    __shared__ float Bs[2][32][68];
    int m0 = blockIdx.x * 64;
    int n0 = blockIdx.y * 64;
    int kz = blockIdx.z * KSLICE;
    int t = threadIdx.x;
    int tx = t & 15;
    int ty = t >> 4;
    float acc[8][4] = {};

    int ar  = t >> 1;            // A row 0..63
    int ac  = (t & 1) * 16;
    int bkk = t >> 2;            // B k-row 0..31
    int bnb = (t & 3) * 16;      // B n sub-base

    const float* Ag = &Cin[(m0 + ar) * H_DIM + kz + ac];
    const float* Bg = &W[(size_t)(kz + bkk) * H_DIM + n0 + bnb];

    float4 aS[4], bS[4];
    #pragma unroll
    for (int j = 0; j < 4; j++) {
        aS[j] = *reinterpret_cast<const float4*>(Ag + j * 4);
        bS[j] = *reinterpret_cast<const float4*>(Bg + j * 4);
    }
    #pragma unroll
    for (int j = 0; j < 4; j++) {
        int cc = ac + j * 4;
        As[0][cc + 0][ar] = aS[j].x; As[0][cc + 1][ar] = aS[j].y;
        As[0][cc + 2][ar] = aS[j].z; As[0][cc + 3][ar] = aS[j].w;
        *reinterpret_cast<float4*>(&Bs[0][bkk][bnb + j * 4]) = bS[j];
    }
    __syncthreads();

    for (int s = 0; s < NSTEPS; s++) {
        int cur = s & 1;
        int nxt = cur ^ 1;
        if (s + 1 < NSTEPS) {
            int k0n = (s + 1) * 32;
            #pragma unroll
            for (int j = 0; j < 4; j++) {
                aS[j] = *reinterpret_cast<const float4*>(Ag + k0n + j * 4);
                bS[j] = *reinterpret_cast<const float4*>(Bg + (size_t)k0n * H_DIM + j * 4);
            }
        }
        float4 a0 = *reinterpret_cast<const float4*>(&As[cur][0][ty * 8]);
        float4 a1 = *reinterpret_cast<const float4*>(&As[cur][0][ty * 8 + 4]);
        float4 bf = *reinterpret_cast<const float4*>(&Bs[cur][0][tx * 4]);
        #pragma unroll
        for (int kk = 0; kk < 32; kk++) {
            float4 a0n, a1n, bfn;
            if (kk < 31) {
                a0n = *reinterpret_cast<const float4*>(&As[cur][kk + 1][ty * 8]);
                a1n = *reinterpret_cast<const float4*>(&As[cur][kk + 1][ty * 8 + 4]);
                bfn = *reinterpret_cast<const float4*>(&Bs[cur][kk + 1][tx * 4]);
            }
            GEMM_FMA32();
            if (kk < 31) { a0 = a0n; a1 = a1n; bf = bfn; }
        }
        if (s + 1 < NSTEPS) {
            #pragma unroll
            for (int j = 0; j < 4; j++) {
                int cc = ac + j * 4;
                As[nxt][cc + 0][ar] = aS[j].x; As[nxt][cc + 1][ar] = aS[j].y;
                As[nxt][cc + 2][ar] = aS[j].z; As[nxt][cc + 3][ar] = aS[j].w;
                *reinterpret_cast<float4*>(&Bs[nxt][bkk][bnb + j * 4]) = bS[j];
            }
            __syncthreads();
        }
    }
    float* outp = g_g_p[blockIdx.z];
    #pragma unroll
    for (int i = 0; i < 8; i++) {
        float4 v = make_float4(acc[i][0], acc[i][1], acc[i][2], acc[i][3]);
        *reinterpret_cast<float4*>(&outp[(m0 + ty * 8 + i) * H_DIM + n0 + tx * 4]) = v;
    }
}

// ---------------------------------------------------------------------------
// squash: chat = sum_z chat_p[z]; out = (norm/(1+norm)) * chat / sqrt(norm)
__global__ void __launch_bounds__(256) squash_kernel(
        float* __restrict__ out,
        const int* __restrict__ itern, int it) {
    if (it >= *itern) return;
    int c = blockIdx.x;
    int t = threadIdx.x;
    __shared__ float red[8];
    int idx = c * (H_DIM / 4) + t;
    float4 v = reinterpret_cast<const float4*>(g_chat_p[0])[idx];
    #pragma unroll
    for (int z = 1; z < KSPLIT; z++) {
        float4 p = reinterpret_cast<const float4*>(g_chat_p[z])[idx];
        v.x += p.x; v.y += p.y; v.z += p.z; v.w += p.w;
    }
    float s = v.x * v.x + v.y * v.y + v.z * v.z + v.w * v.w;
    #pragma unroll
    for (int o = 16; o; o >>= 1) s += __shfl_down_sync(0xffffffffu, s, o);
    if ((t & 31) == 0) red[t >> 5] = s;
    __syncthreads();
    if (t < 32) {
        float r = (t < 8) ? red[t] : 0.0f;
        #pragma unroll
        for (int o = 4; o; o >>= 1) r += __shfl_down_sync(0xffffffffu, r, o);
        if (t == 0) red[0] = r;
    }
    __syncthreads();
    float norm = red[0];
    float scale = (norm / (1.0f + norm)) * rsqrtf(norm);
    float4 o4 = make_float4(scale * v.x, scale * v.y, scale * v.z, scale * v.w);
    reinterpret_cast<float4*>(out)[idx] = o4;
}

// ---------------------------------------------------------------------------
extern "C" void kernel_launch(void* const* d_in, const int* in_sizes, int n_in,
                              void* d_out, int out_size) {
    const float* enc   = (const float*)d_in[0];   // [C, K, H]
    const float* W     = (const float*)d_in[1];   // [H, H]
    const int*   itern = (const int*)d_in[2];     // scalar iter_routing
    float* out = (float*)d_out;                   // [C, H]

    dim3 gemm_grid(C_CAPS / 64, H_DIM / 64, KSPLIT);   // (4, 16, 8) = 512 blocks
    for (int it = 0; it < MAX_ITERS; it++) {
        route_kernel<<<C_CAPS, 256>>>(enc, itern, it);
        gemm_nt_kernel<<<gemm_grid, 128>>>(W, itern, it);
        squash_kernel<<<C_CAPS, 256>>>(out, itern, it);
        gemm_nn_kernel<<<gemm_grid, 128>>>(W, out, itern, it);
    }
}

// round 8
// speedup vs baseline: 2.9874x; 1.3619x over previous
#include <cuda_runtime.h>
#include <cuda_bf16.h>
#include <math.h>
#include <stdint.h>

#define C_CAPS 256
#define K_CAPS 64
#define H_DIM  1024
#define MAX_ITERS 4
#define KSPLIT 2
#define KSPC   (H_DIM / KSPLIT)   // 512 K per CTA
#define KSTEPS (KSPC / 32)        // 16
#define TSTRIDE 40                // bf16 elems per smem tile row (80B, 16B-mult, bank-skewed)
#define TILE_ELEMS (64 * TSTRIDE)

// ---------------------------------------------------------------------------
// Device scratch (no allocation allowed)
__device__ __align__(16) float g_b[C_CAPS * K_CAPS];
__device__ __align__(16) float g_chat_p[KSPLIT][C_CAPS * H_DIM];
__device__ __align__(16) float g_g_p[KSPLIT][C_CAPS * H_DIM];
__device__ __align__(16) __nv_bfloat16 g_e_hi[C_CAPS * H_DIM];
__device__ __align__(16) __nv_bfloat16 g_e_lo[C_CAPS * H_DIM];
__device__ __align__(16) __nv_bfloat16 g_c_hi[C_CAPS * H_DIM];
__device__ __align__(16) __nv_bfloat16 g_c_lo[C_CAPS * H_DIM];
__device__ __align__(16) __nv_bfloat16 g_Wn_hi[H_DIM * H_DIM];   // W[d][h] as-is  (B for NT)
__device__ __align__(16) __nv_bfloat16 g_Wn_lo[H_DIM * H_DIM];
__device__ __align__(16) __nv_bfloat16 g_Wt_hi[H_DIM * H_DIM];   // W^T[h][d]      (B for NN)
__device__ __align__(16) __nv_bfloat16 g_Wt_lo[H_DIM * H_DIM];

// ---------------------------------------------------------------------------
__device__ __forceinline__ uint32_t smem_to_u32(const void* p) {
    uint32_t a;
    asm("{ .reg .u64 t; cvta.to.shared.u64 t, %1; cvt.u32.u64 %0, t; }"
        : "=r"(a) : "l"(p));
    return a;
}
#define CP16(sa, gp) \
    asm volatile("cp.async.cg.shared.global [%0], [%1], 16;" \
        :: "r"((uint32_t)(sa)), "l"(gp) : "memory")
#define CP_COMMIT() asm volatile("cp.async.commit_group;" ::: "memory")
#define CP_WAIT1()  asm volatile("cp.async.wait_group 1;" ::: "memory")
#define CP_WAIT0()  asm volatile("cp.async.wait_group 0;" ::: "memory")
#define LDSM4(r, addr) \
    asm volatile("ldmatrix.sync.aligned.m8n8.x4.shared.b16 {%0,%1,%2,%3}, [%4];" \
        : "=r"((r)[0]), "=r"((r)[1]), "=r"((r)[2]), "=r"((r)[3]) : "r"(addr))
#define LDSM2(r, addr) \
    asm volatile("ldmatrix.sync.aligned.m8n8.x2.shared.b16 {%0,%1}, [%2];" \
        : "=r"((r)[0]), "=r"((r)[1]) : "r"(addr))
#define MMA16816(acc, a, b) \
    asm volatile("mma.sync.aligned.m16n8k16.row.col.f32.bf16.bf16.f32 " \
        "{%0,%1,%2,%3}, {%4,%5,%6,%7}, {%8,%9}, {%0,%1,%2,%3};" \
        : "+f"((acc)[0]), "+f"((acc)[1]), "+f"((acc)[2]), "+f"((acc)[3]) \
        : "r"((a)[0]), "r"((a)[1]), "r"((a)[2]), "r"((a)[3]), \
          "r"((b)[0]), "r"((b)[1]))

__device__ __forceinline__ void split4_store(__nv_bfloat16* hi, __nv_bfloat16* lo,
                                             int idx, float4 v) {
    __nv_bfloat16 h0 = __float2bfloat16(v.x), h1 = __float2bfloat16(v.y);
    __nv_bfloat16 h2 = __float2bfloat16(v.z), h3 = __float2bfloat16(v.w);
    __nv_bfloat16 l0 = __float2bfloat16(v.x - __bfloat162float(h0));
    __nv_bfloat16 l1 = __float2bfloat16(v.y - __bfloat162float(h1));
    __nv_bfloat16 l2 = __float2bfloat16(v.z - __bfloat162float(h2));
    __nv_bfloat16 l3 = __float2bfloat16(v.w - __bfloat162float(h3));
    *reinterpret_cast<__nv_bfloat162*>(hi + idx)     = __halves2bfloat162(h0, h1);
    *reinterpret_cast<__nv_bfloat162*>(hi + idx + 2) = __halves2bfloat162(h2, h3);
    *reinterpret_cast<__nv_bfloat162*>(lo + idx)     = __halves2bfloat162(l0, l1);
    *reinterpret_cast<__nv_bfloat162*>(lo + idx + 2) = __halves2bfloat162(l2, l3);
}

// ---------------------------------------------------------------------------
// One-time W conversion: Wn = bf16 split of W; Wt = split of W^T.
__global__ void __launch_bounds__(256) convert_w_kernel(const float* __restrict__ W) {
    __shared__ float tile[32][33];
    int h0 = blockIdx.x * 32, d0 = blockIdx.y * 32;
    int tx = threadIdx.x, ty = threadIdx.y;   // (32, 8)
    #pragma unroll
    for (int i = 0; i < 4; i++) {
        int d = d0 + ty + i * 8;
        float v = W[(size_t)d * H_DIM + h0 + tx];
        tile[ty + i * 8][tx] = v;
        __nv_bfloat16 h = __float2bfloat16(v);
        g_Wn_hi[(size_t)d * H_DIM + h0 + tx] = h;
        g_Wn_lo[(size_t)d * H_DIM + h0 + tx] = __float2bfloat16(v - __bfloat162float(h));
    }
    __syncthreads();
    #pragma unroll
    for (int i = 0; i < 4; i++) {
        int hh = h0 + ty + i * 8;
        float v = tile[tx][ty + i * 8];
        __nv_bfloat16 h = __float2bfloat16(v);
        g_Wt_hi[(size_t)hh * H_DIM + d0 + tx] = h;
        g_Wt_lo[(size_t)hh * H_DIM + d0 + tx] = __float2bfloat16(v - __bfloat162float(h));
    }
}

// ---------------------------------------------------------------------------
// Fused routing step for capsule c (g = sum of partials; writes bf16 split of e)
__global__ void __launch_bounds__(256) route_kernel(
        const float* __restrict__ enc,
        const int* __restrict__ itern, int it) {
    if (it >= *itern) return;
    int c = blockIdx.x;
    int t = threadIdx.x;
    int warp = t >> 5, lane = t & 31;
    __shared__ __align__(16) float gsh[H_DIM];
    __shared__ float dsh[K_CAPS];
    const float* base = enc + (size_t)c * K_CAPS * H_DIM;

    if (it == 0) {
        if (t < K_CAPS) { dsh[t] = 1.0f / (float)K_CAPS; g_b[c * K_CAPS + t] = 0.0f; }
        __syncthreads();
    } else {
        for (int h = t; h < H_DIM; h += 256)
            gsh[h] = g_g_p[0][c * H_DIM + h] + g_g_p[1][c * H_DIM + h];
        __syncthreads();
        const float4* g4 = reinterpret_cast<const float4*>(gsh);
        for (int k = warp; k < K_CAPS; k += 8) {
            const float4* row4 = reinterpret_cast<const float4*>(base + (size_t)k * H_DIM);
            float s = 0.0f;
            #pragma unroll
            for (int i = lane; i < H_DIM / 4; i += 32) {
                float4 a = row4[i];
                float4 b = g4[i];
                s += a.x * b.x + a.y * b.y + a.z * b.z + a.w * b.w;
            }
            #pragma unroll
            for (int o = 16; o; o >>= 1) s += __shfl_down_sync(0xffffffffu, s, o);
            if (lane == 0) {
                float bn = g_b[c * K_CAPS + k] + s;
                g_b[c * K_CAPS + k] = bn;
                dsh[k] = bn;
            }
        }
        __syncthreads();
        float m = -INFINITY;
        #pragma unroll
        for (int k = 0; k < K_CAPS; k++) m = fmaxf(m, dsh[k]);
        float sum = 0.0f;
        #pragma unroll
        for (int k = 0; k < K_CAPS; k++) sum += expf(dsh[k] - m);
        float inv = 1.0f / sum;
        __syncthreads();
        if (t < K_CAPS) dsh[t] = expf(dsh[t] - m) * inv;
        __syncthreads();
    }

    const float4* b4 = reinterpret_cast<const float4*>(base);
    float4 acc = make_float4(0.f, 0.f, 0.f, 0.f);
    #pragma unroll 8
    for (int k = 0; k < K_CAPS; k++) {
        float d = dsh[k];
        float4 v = b4[k * (H_DIM / 4) + t];
        acc.x += d * v.x; acc.y += d * v.y; acc.z += d * v.z; acc.w += d * v.w;
    }
    split4_store(g_e_hi, g_e_lo, c * H_DIM + t * 4, acc);
}

// ---------------------------------------------------------------------------
// Tensor-core GEMM (mma.sync bf16 3-term split), NT form: D[m,n] = sum_k A[m,k]*B[n,k]
// which==0: A=e (gate it<itern),  B=Wn, out=g_chat_p[z]
// which==1: A=c (gate it+1<itern), B=Wt, out=g_g_p[z]
// CTA: 64x64 tile, 4 warps (2x2 of 32x32), K-split via blockIdx.z.
__global__ void __launch_bounds__(128) gemm_tc_kernel(
        const int* __restrict__ itern, int it, int which) {
    if (it + which >= *itern) return;
    const __nv_bfloat16 *Ahi, *Alo, *Bhi, *Blo;
    float* outp;
    if (which == 0) {
        Ahi = g_e_hi; Alo = g_e_lo; Bhi = g_Wn_hi; Blo = g_Wn_lo;
        outp = g_chat_p[blockIdx.z];
    } else {
        Ahi = g_c_hi; Alo = g_c_lo; Bhi = g_Wt_hi; Blo = g_Wt_lo;
        outp = g_g_p[blockIdx.z];
    }

    // tiles: 0=A_hi 1=A_lo 2=B_hi 3=B_lo
    __shared__ __align__(16) __nv_bfloat16 sm[2][4][TILE_ELEMS];
    uint32_t sbase = smem_to_u32(sm);

    int t = threadIdx.x, wid = t >> 5, lane = t & 31;
    int m0 = blockIdx.x * 64, n0 = blockIdx.y * 64;
    int kz = blockIdx.z * KSPC;
    int wm = wid >> 1, wn = wid & 1;

    // ---- cp.async geometry: thread t loads row t>>1, half (t&1) of each tile.
    // Each k-chunk carries 64 bytes/row; half lh covers bytes [lh*32, lh*32+32).
    int lr = t >> 1, lh = t & 1;
    const char* srcs[4] = {
        (const char*)(Ahi + (size_t)(m0 + lr) * H_DIM),
        (const char*)(Alo + (size_t)(m0 + lr) * H_DIM),
        (const char*)(Bhi + (size_t)(n0 + lr) * H_DIM),
        (const char*)(Blo + (size_t)(n0 + lr) * H_DIM)
    };
    uint32_t dst_off = (uint32_t)(lr * (TSTRIDE * 2) + lh * 32);   // FIXED (was lh*64)
    int src_half = kz * 2 + lh * 32;   // byte offset within row for half lh

    auto load_chunk = [&](int s, int buf) {
        int so = src_half + s * 64;
        #pragma unroll
        for (int i = 0; i < 4; i++) {
            uint32_t d = sbase + (uint32_t)(((buf * 4 + i) * TILE_ELEMS) * 2) + dst_off;
            CP16(d,      srcs[i] + so);
            CP16(d + 16, srcs[i] + so + 16);
        }
    };

    // ---- ldmatrix per-lane offsets (byte offsets within a tile)
    // A x4 (16x16): row = wm*32 + mt*16 + (lane&15), col8 = 8*(lane>>4)
    uint32_t a_off[2];
    #pragma unroll
    for (int mt = 0; mt < 2; mt++)
        a_off[mt] = (uint32_t)((wm * 32 + mt * 16 + (lane & 15)) * (TSTRIDE * 2)
                               + (lane >> 4) * 16);
    // B x2 (8x16): row = wn*32 + nt*8 + (lane&7), col8 = 8*((lane>>3)&1)
    uint32_t b_off[4];
    #pragma unroll
    for (int nt = 0; nt < 4; nt++)
        b_off[nt] = (uint32_t)((wn * 32 + nt * 8 + (lane & 7)) * (TSTRIDE * 2)
                               + ((lane >> 3) & 1) * 16);

    float acc[2][4][4] = {};

    // prologue: chunks 0,1
    load_chunk(0, 0); CP_COMMIT();
    load_chunk(1, 1); CP_COMMIT();

    for (int s = 0; s < KSTEPS; s++) {
        if (s >= KSTEPS - 2) { CP_WAIT0(); } else { CP_WAIT1(); }
        __syncthreads();
        int buf = s & 1;
        uint32_t tb = sbase + (uint32_t)((buf * 4) * TILE_ELEMS * 2);
        uint32_t tAh = tb, tAl = tb + TILE_ELEMS * 2;
        uint32_t tBh = tb + 2 * TILE_ELEMS * 2, tBl = tb + 3 * TILE_ELEMS * 2;

        #pragma unroll
        for (int ksub = 0; ksub < 2; ksub++) {
            uint32_t ko = (uint32_t)(ksub * 32);   // 16 bf16 = 32 bytes
            uint32_t ah[2][4], al[2][4], bh[4][2], bl[4][2];
            #pragma unroll
            for (int mt = 0; mt < 2; mt++) {
                LDSM4(ah[mt], tAh + a_off[mt] + ko);
                LDSM4(al[mt], tAl + a_off[mt] + ko);
            }
            #pragma unroll
            for (int nt = 0; nt < 4; nt++) {
                LDSM2(bh[nt], tBh + b_off[nt] + ko);
                LDSM2(bl[nt], tBl + b_off[nt] + ko);
            }
            #pragma unroll
            for (int mt = 0; mt < 2; mt++)
                #pragma unroll
                for (int nt = 0; nt < 4; nt++) {
                    MMA16816(acc[mt][nt], ah[mt], bh[nt]);
                    MMA16816(acc[mt][nt], ah[mt], bl[nt]);
                    MMA16816(acc[mt][nt], al[mt], bh[nt]);
                }
        }
        __syncthreads();
        if (s + 2 < KSTEPS) { load_chunk(s + 2, buf); CP_COMMIT(); }
    }

    // epilogue: fragment rows gid/gid+8, cols 2*(lane&3)
    int gid = lane >> 2, tig = lane & 3;
    #pragma unroll
    for (int mt = 0; mt < 2; mt++) {
        int r0 = m0 + wm * 32 + mt * 16 + gid;
        #pragma unroll
        for (int nt = 0; nt < 4; nt++) {
            int cc = n0 + wn * 32 + nt * 8 + tig * 2;
            *reinterpret_cast<float2*>(&outp[(size_t)r0 * H_DIM + cc]) =
                make_float2(acc[mt][nt][0], acc[mt][nt][1]);
            *reinterpret_cast<float2*>(&outp[(size_t)(r0 + 8) * H_DIM + cc]) =
                make_float2(acc[mt][nt][2], acc[mt][nt][3]);
        }
    }
}

// ---------------------------------------------------------------------------
// squash: chat = sum_z chat_p; out fp32 + bf16 split of c
__global__ void __launch_bounds__(256) squash_kernel(
        float* __restrict__ out,
        const int* __restrict__ itern, int it) {
    if (it >= *itern) return;
    int c = blockIdx.x;
    int t = threadIdx.x;
    __shared__ float red[8];
    int idx = c * (H_DIM / 4) + t;
    float4 v = reinterpret_cast<const float4*>(g_chat_p[0])[idx];
    float4 p = reinterpret_cast<const float4*>(g_chat_p[1])[idx];
    v.x += p.x; v.y += p.y; v.z += p.z; v.w += p.w;
    float s = v.x * v.x + v.y * v.y + v.z * v.z + v.w * v.w;
    #pragma unroll
    for (int o = 16; o; o >>= 1) s += __shfl_down_sync(0xffffffffu, s, o);
    if ((t & 31) == 0) red[t >> 5] = s;
    __syncthreads();
    if (t < 32) {
        float r = (t < 8) ? red[t] : 0.0f;
        #pragma unroll
        for (int o = 4; o; o >>= 1) r += __shfl_down_sync(0xffffffffu, r, o);
        if (t == 0) red[0] = r;
    }
    __syncthreads();
    float norm = red[0];
    float scale = (norm / (1.0f + norm)) * rsqrtf(norm);
    float4 o4 = make_float4(scale * v.x, scale * v.y, scale * v.z, scale * v.w);
    reinterpret_cast<float4*>(out)[idx] = o4;
    split4_store(g_c_hi, g_c_lo, c * H_DIM + t * 4, o4);
}

// ---------------------------------------------------------------------------
extern "C" void kernel_launch(void* const* d_in, const int* in_sizes, int n_in,
                              void* d_out, int out_size) {
    const float* enc   = (const float*)d_in[0];   // [C, K, H]
    const float* W     = (const float*)d_in[1];   // [H, H]
    const int*   itern = (const int*)d_in[2];     // scalar iter_routing
    float* out = (float*)d_out;                   // [C, H]

    convert_w_kernel<<<dim3(H_DIM / 32, H_DIM / 32), dim3(32, 8)>>>(W);

    dim3 gemm_grid(C_CAPS / 64, H_DIM / 64, KSPLIT);   // (4, 16, 2) = 128 CTAs
    for (int it = 0; it < MAX_ITERS; it++) {
        route_kernel<<<C_CAPS, 256>>>(enc, itern, it);
        gemm_tc_kernel<<<gemm_grid, 128>>>(itern, it, 0);
        squash_kernel<<<C_CAPS, 256>>>(out, itern, it);
        gemm_tc_kernel<<<gemm_grid, 128>>>(itern, it, 1);
    }
}